// round 1
// baseline (speedup 1.0000x reference)
#include <cuda_runtime.h>
#include <math.h>

#define BATCH 512
#define TSTEPS 256
#define INPUT 512
#define HID 128
#define G4 512          // 4*HID
#define FC1DIM 64
#define NACT 10
#define MROWS (BATCH*TSTEPS)   // 131072

// ---------------- scratch (static device memory; no allocs) ----------------
__device__ float g_xproj[(size_t)MROWS * G4];   // 256 MB, reused by both layers
__device__ float g_hseq[(size_t)MROWS * HID];   // 64 MB, layer-0 hidden sequence
__device__ float g_Wt[2][HID * G4];             // Whh transposed to [k][g]

// output layout in d_out (float32):
//   probs [512*10]  | h_n [2*512*128] | c_n [2*512*128]
#define OUT_HN_OFF   (BATCH*NACT)                     // 5120
#define OUT_CN_OFF   (OUT_HN_OFF + 2*BATCH*HID)      // 136192

// ---------------- helpers ----------------
__device__ __forceinline__ float sigmoidf_(float x) {
    return 1.0f / (1.0f + __expf(-x));
}
__device__ __forceinline__ float tanhf_(float x) {
    return 1.0f - 2.0f / (__expf(2.0f * x) + 1.0f);
}

// ---------------- transpose Whh [512][128] -> [128][512] ----------------
__global__ void transpose_whh_kernel(const float* __restrict__ w0,
                                     const float* __restrict__ w1) {
    int idx = blockIdx.x * 256 + threadIdx.x;   // 65536 total
    int k = idx >> 9;        // 0..127
    int g = idx & 511;       // 0..511
    g_Wt[0][k * G4 + g] = w0[g * HID + k];
    g_Wt[1][k * G4 + g] = w1[g * HID + k];
}

// ---------------- fused-bias SGEMM: C[M][512] = A[M][K] @ W[512][K]^T + bih + bhh
template<int K>
__global__ __launch_bounds__(256)
void gemm_bias_kernel(const float* __restrict__ A,
                      const float* __restrict__ W,
                      const float* __restrict__ bih,
                      const float* __restrict__ bhh,
                      float* __restrict__ C) {
    __shared__ float As[16][128];
    __shared__ float Ws[16][128];

    const int tx = threadIdx.x & 15;
    const int ty = threadIdx.x >> 4;
    const int m0 = blockIdx.y * 128;
    const int n0 = blockIdx.x * 128;

    const int lrow = threadIdx.x >> 2;        // 0..63
    const int lcol = (threadIdx.x & 3) * 4;   // 0,4,8,12

    float acc[8][8];
#pragma unroll
    for (int i = 0; i < 8; ++i)
#pragma unroll
        for (int j = 0; j < 8; ++j) acc[i][j] = 0.0f;

    for (int kt = 0; kt < K; kt += 16) {
        float4 a0 = *(const float4*)&A[(m0 + lrow) * K + kt + lcol];
        float4 a1 = *(const float4*)&A[(m0 + 64 + lrow) * K + kt + lcol];
        float4 w0 = *(const float4*)&W[(n0 + lrow) * K + kt + lcol];
        float4 w1 = *(const float4*)&W[(n0 + 64 + lrow) * K + kt + lcol];
        __syncthreads();
        As[lcol + 0][lrow] = a0.x; As[lcol + 1][lrow] = a0.y;
        As[lcol + 2][lrow] = a0.z; As[lcol + 3][lrow] = a0.w;
        As[lcol + 0][64 + lrow] = a1.x; As[lcol + 1][64 + lrow] = a1.y;
        As[lcol + 2][64 + lrow] = a1.z; As[lcol + 3][64 + lrow] = a1.w;
        Ws[lcol + 0][lrow] = w0.x; Ws[lcol + 1][lrow] = w0.y;
        Ws[lcol + 2][lrow] = w0.z; Ws[lcol + 3][lrow] = w0.w;
        Ws[lcol + 0][64 + lrow] = w1.x; Ws[lcol + 1][64 + lrow] = w1.y;
        Ws[lcol + 2][64 + lrow] = w1.z; Ws[lcol + 3][64 + lrow] = w1.w;
        __syncthreads();
#pragma unroll
        for (int kk = 0; kk < 16; ++kk) {
            float a[8], b[8];
            *(float4*)&a[0] = *(const float4*)&As[kk][ty * 4];
            *(float4*)&a[4] = *(const float4*)&As[kk][64 + ty * 4];
            *(float4*)&b[0] = *(const float4*)&Ws[kk][tx * 4];
            *(float4*)&b[4] = *(const float4*)&Ws[kk][64 + tx * 4];
#pragma unroll
            for (int i = 0; i < 8; ++i)
#pragma unroll
                for (int j = 0; j < 8; ++j)
                    acc[i][j] += a[i] * b[j];
        }
    }

    // bias vectors for the two column groups
    float4 bihA = *(const float4*)&bih[n0 + tx * 4];
    float4 bhhA = *(const float4*)&bhh[n0 + tx * 4];
    float4 bihB = *(const float4*)&bih[n0 + 64 + tx * 4];
    float4 bhhB = *(const float4*)&bhh[n0 + 64 + tx * 4];
    float bA[4] = {bihA.x + bhhA.x, bihA.y + bhhA.y, bihA.z + bhhA.z, bihA.w + bhhA.w};
    float bB[4] = {bihB.x + bhhB.x, bihB.y + bhhB.y, bihB.z + bhhB.z, bihB.w + bhhB.w};

#pragma unroll
    for (int i = 0; i < 8; ++i) {
        int row = m0 + ((i < 4) ? (ty * 4 + i) : (64 + ty * 4 + i - 4));
        float4 v0, v1;
        v0.x = acc[i][0] + bA[0]; v0.y = acc[i][1] + bA[1];
        v0.z = acc[i][2] + bA[2]; v0.w = acc[i][3] + bA[3];
        v1.x = acc[i][4] + bB[0]; v1.y = acc[i][5] + bB[1];
        v1.z = acc[i][6] + bB[2]; v1.w = acc[i][7] + bB[3];
        *(float4*)&C[row * G4 + n0 + tx * 4] = v0;
        *(float4*)&C[row * G4 + n0 + 64 + tx * 4] = v1;
    }
}

// ---------------- LSTM recurrence ----------------
// 128 blocks x 256 threads; block owns 4 batch rows for all 256 steps.
// smem: Wsm[k][0..383] (i,f,g gates of Whh^T, 192KB) + partials (32KB) + h (2KB)
// o-gate weights streamed from L2 each step.
#define LSTM_SMEM_FLOATS (128*384 + 4*4*512 + 4*128)   // 57856 floats = 231424 B

template<int LAYER>
__global__ __launch_bounds__(256, 1)
void lstm_kernel(const float* __restrict__ xproj,
                 float* __restrict__ hseq,
                 float* __restrict__ out) {
    extern __shared__ float smem[];
    float* Wsm  = smem;                       // [128][384]
    float* part = smem + 128 * 384;           // [4 ksl][4 row][512 gate]
    float* hbuf = part + 4 * 4 * 512;         // [4 row][128]

    const float* Wt = g_Wt[LAYER];            // [128][512]
    const int tid = threadIdx.x;
    const int b0 = blockIdx.x * 4;

    // stage i,f,g gate weights (transposed) into smem
    for (int i = tid; i < 128 * 384 / 4; i += 256) {
        int k = i / 96;
        int gc4 = (i % 96) * 4;
        *(float4*)&Wsm[k * 384 + gc4] = *(const float4*)&Wt[k * G4 + gc4];
    }
    for (int i = tid; i < 4 * 128; i += 256) hbuf[i] = 0.0f;
    float creg[2] = {0.0f, 0.0f};
    __syncthreads();

    const int ksl  = tid >> 6;     // 0..3 (k-slice)
    const int ggrp = tid & 63;     // 0..63
    const int k0   = ksl * 32;

    for (int t = 0; t < TSTEPS; ++t) {
        // prefetch x_proj contributions for this thread's activation cells
        float xv[2][4];
#pragma unroll
        for (int cc = 0; cc < 2; ++cc) {
            int cell = tid + cc * 256;
            int r = cell >> 7, hc = cell & 127;
            const float* xp = xproj + ((b0 + r) * TSTEPS + t) * G4 + hc;
            xv[cc][0] = xp[0];   xv[cc][1] = xp[128];
            xv[cc][2] = xp[256]; xv[cc][3] = xp[384];
        }

        // partial GEMM: acc[row][j] over this thread's 32-k slice
        float acc[4][8];
#pragma unroll
        for (int r = 0; r < 4; ++r)
#pragma unroll
            for (int j = 0; j < 8; ++j) acc[r][j] = 0.0f;

#pragma unroll 8
        for (int kk = 0; kk < 32; ++kk) {
            int k = k0 + kk;
            float h0 = hbuf[k];
            float h1 = hbuf[128 + k];
            float h2 = hbuf[256 + k];
            float h3 = hbuf[384 + k];
#pragma unroll
            for (int j = 0; j < 8; ++j) {
                int g = ggrp + 64 * j;
                float w = (j < 6) ? Wsm[k * 384 + g]
                                  : __ldg(&Wt[k * G4 + g]);
                acc[0][j] += h0 * w;
                acc[1][j] += h1 * w;
                acc[2][j] += h2 * w;
                acc[3][j] += h3 * w;
            }
        }
#pragma unroll
        for (int j = 0; j < 8; ++j) {
            int g = ggrp + 64 * j;
#pragma unroll
            for (int r = 0; r < 4; ++r)
                part[(ksl * 4 + r) * 512 + g] = acc[r][j];
        }
        __syncthreads();

        // reduce + gates + state update
#pragma unroll
        for (int cc = 0; cc < 2; ++cc) {
            int cell = tid + cc * 256;
            int r = cell >> 7, hc = cell & 127;
            float gi = xv[cc][0], gf = xv[cc][1], gg = xv[cc][2], go = xv[cc][3];
#pragma unroll
            for (int s = 0; s < 4; ++s) {
                const float* p = &part[(s * 4 + r) * 512];
                gi += p[hc];
                gf += p[128 + hc];
                gg += p[256 + hc];
                go += p[384 + hc];
            }
            float iv = sigmoidf_(gi);
            float fv = sigmoidf_(gf);
            float gv = tanhf_(gg);
            float ov = sigmoidf_(go);
            float c = fv * creg[cc] + iv * gv;
            creg[cc] = c;
            float h = ov * tanhf_(c);
            hbuf[r * 128 + hc] = h;
            if (LAYER == 0)
                hseq[((b0 + r) * TSTEPS + t) * HID + hc] = h;
        }
        __syncthreads();
    }

    // final h_n / c_n
#pragma unroll
    for (int cc = 0; cc < 2; ++cc) {
        int cell = tid + cc * 256;
        int r = cell >> 7, hc = cell & 127;
        int bi = b0 + r;
        out[OUT_HN_OFF + LAYER * BATCH * HID + bi * HID + hc] = hbuf[r * 128 + hc];
        out[OUT_CN_OFF + LAYER * BATCH * HID + bi * HID + hc] = creg[cc];
    }
}

// ---------------- head: relu(h@fc1^T+b1)@fc2^T+b2 -> softmax ----------------
__global__ __launch_bounds__(256)
void head_kernel(const float* __restrict__ fc1w, const float* __restrict__ fc1b,
                 const float* __restrict__ fc2w, const float* __restrict__ fc2b,
                 float* __restrict__ out) {
    __shared__ float sw1[FC1DIM * HID];    // 32 KB
    __shared__ float sw2[NACT * FC1DIM];
    __shared__ float sb1[FC1DIM];
    __shared__ float sb2[NACT];

    for (int i = threadIdx.x; i < FC1DIM * HID; i += 256) sw1[i] = fc1w[i];
    for (int i = threadIdx.x; i < NACT * FC1DIM; i += 256) sw2[i] = fc2w[i];
    if (threadIdx.x < FC1DIM) sb1[threadIdx.x] = fc1b[threadIdx.x];
    if (threadIdx.x < NACT) sb2[threadIdx.x] = fc2b[threadIdx.x];
    __syncthreads();

    int row = blockIdx.x * 256 + threadIdx.x;   // 0..511
    const float* h = out + OUT_HN_OFF + BATCH * HID + row * HID;  // h_n[1]

    float hid[FC1DIM];
#pragma unroll
    for (int j = 0; j < FC1DIM; ++j) hid[j] = sb1[j];
    for (int k = 0; k < HID; ++k) {
        float hv = h[k];
#pragma unroll
        for (int j = 0; j < FC1DIM; ++j)
            hid[j] += hv * sw1[j * HID + k];
    }
#pragma unroll
    for (int j = 0; j < FC1DIM; ++j) hid[j] = fmaxf(hid[j], 0.0f);

    float logit[NACT];
    float mx = -1e30f;
#pragma unroll
    for (int a = 0; a < NACT; ++a) {
        float l = sb2[a];
#pragma unroll
        for (int j = 0; j < FC1DIM; ++j)
            l += hid[j] * sw2[a * FC1DIM + j];
        logit[a] = l;
        mx = fmaxf(mx, l);
    }
    float sum = 0.0f;
#pragma unroll
    for (int a = 0; a < NACT; ++a) {
        logit[a] = __expf(logit[a] - mx);
        sum += logit[a];
    }
    float inv = 1.0f / sum;
#pragma unroll
    for (int a = 0; a < NACT; ++a)
        out[row * NACT + a] = logit[a] * inv;
}

// ---------------- launch ----------------
extern "C" void kernel_launch(void* const* d_in, const int* in_sizes, int n_in,
                              void* d_out, int out_size) {
    (void)in_sizes; (void)n_in; (void)out_size;
    const float* x     = (const float*)d_in[0];
    const float* Wih0  = (const float*)d_in[1];
    const float* Whh0  = (const float*)d_in[2];
    const float* bih0  = (const float*)d_in[3];
    const float* bhh0  = (const float*)d_in[4];
    const float* Wih1  = (const float*)d_in[5];
    const float* Whh1  = (const float*)d_in[6];
    const float* bih1  = (const float*)d_in[7];
    const float* bhh1  = (const float*)d_in[8];
    const float* fc1w  = (const float*)d_in[9];
    const float* fc1b  = (const float*)d_in[10];
    const float* fc2w  = (const float*)d_in[11];
    const float* fc2b  = (const float*)d_in[12];
    float* out = (float*)d_out;

    float* xproj = nullptr;
    float* hseq  = nullptr;
    cudaGetSymbolAddress((void**)&xproj, g_xproj);
    cudaGetSymbolAddress((void**)&hseq, g_hseq);

    cudaFuncSetAttribute(lstm_kernel<0>,
                         cudaFuncAttributeMaxDynamicSharedMemorySize,
                         LSTM_SMEM_FLOATS * 4);
    cudaFuncSetAttribute(lstm_kernel<1>,
                         cudaFuncAttributeMaxDynamicSharedMemorySize,
                         LSTM_SMEM_FLOATS * 4);

    // 1) transpose Whh for both layers
    transpose_whh_kernel<<<256, 256>>>(Whh0, Whh1);

    // 2) x_proj0 = x @ Wih0^T + bih0 + bhh0
    gemm_bias_kernel<INPUT><<<dim3(4, MROWS / 128), 256>>>(x, Wih0, bih0, bhh0, xproj);

    // 3) layer-0 recurrence
    lstm_kernel<0><<<BATCH / 4, 256, LSTM_SMEM_FLOATS * 4>>>(xproj, hseq, out);

    // 4) x_proj1 = h0_seq @ Wih1^T + bih1 + bhh1
    gemm_bias_kernel<HID><<<dim3(4, MROWS / 128), 256>>>(hseq, Wih1, bih1, bhh1, xproj);

    // 5) layer-1 recurrence
    lstm_kernel<1><<<BATCH / 4, 256, LSTM_SMEM_FLOATS * 4>>>(xproj, nullptr, out);

    // 6) head
    head_kernel<<<2, 256>>>(fc1w, fc1b, fc2w, fc2b, out);
}

// round 5
// speedup vs baseline: 1.3448x; 1.3448x over previous
// R5: identical to R4 (mma.sync bf16 hi/lo GEMM) — resubmitted after opaque
// container failure; R2->R3 precedent says flakes reproduce as real errors
// on resubmit if they are real.
#include <cuda_runtime.h>
#include <cuda_bf16.h>
#include <cstdint>
#include <math.h>

#define BATCH 512
#define TSTEPS 256
#define INPUT 512
#define HID 128
#define G4 512          // 4*HID
#define FC1DIM 64
#define NACT 10
#define MROWS (BATCH*TSTEPS)   // 131072

// ---------------- scratch (static device memory; no allocs) ----------------
__device__ float g_xproj[(size_t)MROWS * G4];   // 256 MB, reused by both layers
__device__ float g_hseq[(size_t)MROWS * HID];   // 64 MB, layer-0 hidden sequence
__device__ float g_Wt[2][HID * G4];             // Whh transposed to [k][g]
__device__ __nv_bfloat16 g_Wih0_hi[G4 * INPUT];
__device__ __nv_bfloat16 g_Wih0_lo[G4 * INPUT];
__device__ __nv_bfloat16 g_Wih1_hi[G4 * HID];
__device__ __nv_bfloat16 g_Wih1_lo[G4 * HID];

// output layout in d_out (float32):
//   probs [512*10]  | h_n [2*512*128] | c_n [2*512*128]
#define OUT_HN_OFF   (BATCH*NACT)                     // 5120
#define OUT_CN_OFF   (OUT_HN_OFF + 2*BATCH*HID)      // 136192

// ---------------- helpers ----------------
__device__ __forceinline__ float sigmoidf_(float x) {
    return 1.0f / (1.0f + __expf(-x));
}
__device__ __forceinline__ float tanhf_(float x) {
    return 1.0f - 2.0f / (__expf(2.0f * x) + 1.0f);
}
__device__ __forceinline__ uint32_t smem_u32(const void* p) {
    uint32_t a;
    asm("{ .reg .u64 t; cvta.to.shared.u64 t, %1; cvt.u32.u64 %0, t; }"
        : "=r"(a) : "l"(p));
    return a;
}
__device__ __forceinline__ uint32_t pack_bf16(float a, float b) {
    __nv_bfloat162 t = __floats2bfloat162_rn(a, b);
    return *reinterpret_cast<uint32_t*>(&t);
}
__device__ __forceinline__ void ldsm_x4(uint32_t& r0, uint32_t& r1,
                                        uint32_t& r2, uint32_t& r3,
                                        uint32_t addr) {
    asm volatile("ldmatrix.sync.aligned.m8n8.x4.shared.b16 {%0,%1,%2,%3}, [%4];"
                 : "=r"(r0), "=r"(r1), "=r"(r2), "=r"(r3) : "r"(addr));
}
__device__ __forceinline__ void mma16816(float* c, uint32_t a0, uint32_t a1,
                                         uint32_t a2, uint32_t a3,
                                         uint32_t b0, uint32_t b1) {
    asm volatile(
        "mma.sync.aligned.m16n8k16.row.col.f32.bf16.bf16.f32 "
        "{%0,%1,%2,%3}, {%4,%5,%6,%7}, {%8,%9}, {%0,%1,%2,%3};"
        : "+f"(c[0]), "+f"(c[1]), "+f"(c[2]), "+f"(c[3])
        : "r"(a0), "r"(a1), "r"(a2), "r"(a3), "r"(b0), "r"(b1));
}

// ---------------- weight prep: transpose Whh + split Wih to bf16 hi/lo ----
__global__ void prep_weights_kernel(const float* __restrict__ whh0,
                                    const float* __restrict__ whh1,
                                    const float* __restrict__ wih0,
                                    const float* __restrict__ wih1) {
    int idx = blockIdx.x * 256 + threadIdx.x;   // up to 262144
    if (idx < 65536) {
        int k = idx >> 9;
        int g = idx & 511;
        g_Wt[0][k * G4 + g] = whh0[g * HID + k];
        g_Wt[1][k * G4 + g] = whh1[g * HID + k];
    }
    if (idx < G4 * INPUT) {
        float v = wih0[idx];
        __nv_bfloat16 h = __float2bfloat16(v);
        g_Wih0_hi[idx] = h;
        g_Wih0_lo[idx] = __float2bfloat16(v - __bfloat162float(h));
    }
    if (idx < G4 * HID) {
        float v = wih1[idx];
        __nv_bfloat16 h = __float2bfloat16(v);
        g_Wih1_hi[idx] = h;
        g_Wih1_lo[idx] = __float2bfloat16(v - __bfloat162float(h));
    }
}

// ---------------- mma.sync bf16 GEMM: C[M][512] = A[M][K] @ W[512][K]^T + bias
// CTA tile 128x128, BK=32, 256 threads (8 warps, warp tile 64x32).
// bf16 hi/lo 3-pass (Ahi*Whi + Ahi*Wlo + Alo*Whi), fp32 accumulate.
// smem stride 40 bf16 (80B): conflict-free ldmatrix, 16B-aligned k-offsets.
#define SSTR 40
#define SM_AHI 0
#define SM_ALO (128*SSTR)
#define SM_WHI (2*128*SSTR)
#define SM_WLO (3*128*SSTR)

template<int K>
__global__ __launch_bounds__(256)
void gemm_mma_kernel(const float* __restrict__ A,
                     const __nv_bfloat16* __restrict__ Whi,
                     const __nv_bfloat16* __restrict__ Wlo,
                     const float* __restrict__ bih,
                     const float* __restrict__ bhh,
                     float* __restrict__ C) {
    __shared__ __align__(16) __nv_bfloat16 sm[4 * 128 * SSTR];   // 40960 B

    const int tid = threadIdx.x;
    const int wid = tid >> 5;
    const int lane = tid & 31;
    const int wm = wid & 1;          // 0..1 : M
    const int wn = wid >> 1;         // 0..3 : N
    const int m0 = blockIdx.y * 128;
    const int n0 = blockIdx.x * 128;
    constexpr int NCH = K / 32;

    const uint32_t smb = smem_u32(sm);

    float acc[4][4][4];
#pragma unroll
    for (int mf = 0; mf < 4; ++mf)
#pragma unroll
        for (int nf = 0; nf < 4; ++nf)
#pragma unroll
            for (int i = 0; i < 4; ++i) acc[mf][nf][i] = 0.0f;

    // staging regs
    float4 av[4];
    uint2 wh[4], wl[4];

    // ---- load chunk 0
    {
#pragma unroll
        for (int q = 0; q < 4; ++q) {
            int idx = tid + q * 256;
            int r = idx >> 3, c4 = (idx & 7) * 4;
            av[q] = *reinterpret_cast<const float4*>(&A[(size_t)(m0 + r) * K + c4]);
        }
#pragma unroll
        for (int q = 0; q < 4; ++q) {
            int idx = tid + q * 256;
            int r = idx >> 3, cc = (idx & 7) * 4;
            wh[q] = *reinterpret_cast<const uint2*>(&Whi[(size_t)(n0 + r) * K + cc]);
            wl[q] = *reinterpret_cast<const uint2*>(&Wlo[(size_t)(n0 + r) * K + cc]);
        }
    }
    // ---- store chunk 0 to smem
#pragma unroll
    for (int q = 0; q < 4; ++q) {
        int idx = tid + q * 256;
        int r = idx >> 3, c4 = (idx & 7) * 4;
        float4 v = av[q];
        float hx = __bfloat162float(__float2bfloat16(v.x));
        float hy = __bfloat162float(__float2bfloat16(v.y));
        float hz = __bfloat162float(__float2bfloat16(v.z));
        float hw = __bfloat162float(__float2bfloat16(v.w));
        *reinterpret_cast<uint2*>(&sm[SM_AHI + r * SSTR + c4]) =
            make_uint2(pack_bf16(v.x, v.y), pack_bf16(v.z, v.w));
        *reinterpret_cast<uint2*>(&sm[SM_ALO + r * SSTR + c4]) =
            make_uint2(pack_bf16(v.x - hx, v.y - hy), pack_bf16(v.z - hz, v.w - hw));
        *reinterpret_cast<uint2*>(&sm[SM_WHI + r * SSTR + c4]) = wh[q];
        *reinterpret_cast<uint2*>(&sm[SM_WLO + r * SSTR + c4]) = wl[q];
    }
    __syncthreads();

    // lane-derived ldmatrix offsets (in bf16 elems, within tile, before k0)
    const int a_row = (lane & 15);            // + mbase
    const int a_kofs = (lane >> 4) * 8;       // + k0
    const int b_row = (lane & 7) + ((lane >> 4) & 1) * 8;  // + nbase
    const int b_kofs = ((lane >> 3) & 1) * 8;              // + k0

    for (int ch = 0; ch < NCH; ++ch) {
        // prefetch next chunk to regs (in flight during mma)
        if (ch + 1 < NCH) {
            const int kc = (ch + 1) * 32;
#pragma unroll
            for (int q = 0; q < 4; ++q) {
                int idx = tid + q * 256;
                int r = idx >> 3, c4 = (idx & 7) * 4;
                av[q] = *reinterpret_cast<const float4*>(
                    &A[(size_t)(m0 + r) * K + kc + c4]);
            }
#pragma unroll
            for (int q = 0; q < 4; ++q) {
                int idx = tid + q * 256;
                int r = idx >> 3, cc = (idx & 7) * 4;
                wh[q] = *reinterpret_cast<const uint2*>(
                    &Whi[(size_t)(n0 + r) * K + kc + cc]);
                wl[q] = *reinterpret_cast<const uint2*>(
                    &Wlo[(size_t)(n0 + r) * K + kc + cc]);
            }
        }

        // ---- mma over the 2 k-steps of this chunk
#pragma unroll
        for (int kk = 0; kk < 32; kk += 16) {
            // B frags: 4 nf (pairs via x4), hi and lo
            uint32_t bh[8], bl[8];
#pragma unroll
            for (int nfp = 0; nfp < 2; ++nfp) {
                int row = wn * 32 + nfp * 16 + b_row;
                uint32_t off = (uint32_t)(row * SSTR + kk + b_kofs) * 2;
                ldsm_x4(bh[nfp * 4 + 0], bh[nfp * 4 + 1],
                        bh[nfp * 4 + 2], bh[nfp * 4 + 3], smb + SM_WHI * 2 + off);
                ldsm_x4(bl[nfp * 4 + 0], bl[nfp * 4 + 1],
                        bl[nfp * 4 + 2], bl[nfp * 4 + 3], smb + SM_WLO * 2 + off);
            }
#pragma unroll
            for (int mf = 0; mf < 4; ++mf) {
                int row = wm * 64 + mf * 16 + a_row;
                uint32_t off = (uint32_t)(row * SSTR + kk + a_kofs) * 2;
                uint32_t ah0, ah1, ah2, ah3, al0, al1, al2, al3;
                ldsm_x4(ah0, ah1, ah2, ah3, smb + SM_AHI * 2 + off);
                ldsm_x4(al0, al1, al2, al3, smb + SM_ALO * 2 + off);
#pragma unroll
                for (int nf = 0; nf < 4; ++nf) {
                    uint32_t b0h = bh[(nf >> 1) * 4 + (nf & 1) * 2 + 0];
                    uint32_t b1h = bh[(nf >> 1) * 4 + (nf & 1) * 2 + 1];
                    uint32_t b0l = bl[(nf >> 1) * 4 + (nf & 1) * 2 + 0];
                    uint32_t b1l = bl[(nf >> 1) * 4 + (nf & 1) * 2 + 1];
                    mma16816(acc[mf][nf], ah0, ah1, ah2, ah3, b0h, b1h);
                    mma16816(acc[mf][nf], ah0, ah1, ah2, ah3, b0l, b1l);
                    mma16816(acc[mf][nf], al0, al1, al2, al3, b0h, b1h);
                }
            }
        }
        __syncthreads();

        // ---- store prefetched chunk
        if (ch + 1 < NCH) {
#pragma unroll
            for (int q = 0; q < 4; ++q) {
                int idx = tid + q * 256;
                int r = idx >> 3, c4 = (idx & 7) * 4;
                float4 v = av[q];
                float hx = __bfloat162float(__float2bfloat16(v.x));
                float hy = __bfloat162float(__float2bfloat16(v.y));
                float hz = __bfloat162float(__float2bfloat16(v.z));
                float hw = __bfloat162float(__float2bfloat16(v.w));
                *reinterpret_cast<uint2*>(&sm[SM_AHI + r * SSTR + c4]) =
                    make_uint2(pack_bf16(v.x, v.y), pack_bf16(v.z, v.w));
                *reinterpret_cast<uint2*>(&sm[SM_ALO + r * SSTR + c4]) =
                    make_uint2(pack_bf16(v.x - hx, v.y - hy),
                               pack_bf16(v.z - hz, v.w - hw));
                *reinterpret_cast<uint2*>(&sm[SM_WHI + r * SSTR + c4]) = wh[q];
                *reinterpret_cast<uint2*>(&sm[SM_WLO + r * SSTR + c4]) = wl[q];
            }
            __syncthreads();
        }
    }

    // ---- epilogue: bias + store
    const int mbase = m0 + wm * 64;
    const int nbase = n0 + wn * 32;
    float bs0[4], bs1[4];
#pragma unroll
    for (int nf = 0; nf < 4; ++nf) {
        int c = nbase + nf * 8 + (lane & 3) * 2;
        bs0[nf] = bih[c] + bhh[c];
        bs1[nf] = bih[c + 1] + bhh[c + 1];
    }
#pragma unroll
    for (int mf = 0; mf < 4; ++mf) {
        int row0 = mbase + mf * 16 + (lane >> 2);
#pragma unroll
        for (int nf = 0; nf < 4; ++nf) {
            int col = nbase + nf * 8 + (lane & 3) * 2;
            float2 v0 = make_float2(acc[mf][nf][0] + bs0[nf],
                                    acc[mf][nf][1] + bs1[nf]);
            float2 v1 = make_float2(acc[mf][nf][2] + bs0[nf],
                                    acc[mf][nf][3] + bs1[nf]);
            *reinterpret_cast<float2*>(&C[(size_t)row0 * G4 + col]) = v0;
            *reinterpret_cast<float2*>(&C[(size_t)(row0 + 8) * G4 + col]) = v1;
        }
    }
}

// ---------------- LSTM recurrence (unchanged) ----------------
#define LSTM_SMEM_FLOATS (128*384 + 4*4*512 + 4*128)   // 57856 floats = 231424 B

template<int LAYER>
__global__ __launch_bounds__(256, 1)
void lstm_kernel(const float* __restrict__ xproj,
                 float* __restrict__ hseq,
                 float* __restrict__ out) {
    extern __shared__ float smemf[];
    float* Wsm  = smemf;                      // [128][384]
    float* part = smemf + 128 * 384;          // [4 ksl][4 row][512 gate]
    float* hbuf = part + 4 * 4 * 512;         // [4 row][128]

    const float* Wt = g_Wt[LAYER];            // [128][512]
    const int tid = threadIdx.x;
    const int b0 = blockIdx.x * 4;

    for (int i = tid; i < 128 * 384 / 4; i += 256) {
        int k = i / 96;
        int gc4 = (i % 96) * 4;
        *(float4*)&Wsm[k * 384 + gc4] = *(const float4*)&Wt[k * G4 + gc4];
    }
    for (int i = tid; i < 4 * 128; i += 256) hbuf[i] = 0.0f;
    float creg[2] = {0.0f, 0.0f};
    __syncthreads();

    const int ksl  = tid >> 6;
    const int ggrp = tid & 63;
    const int k0   = ksl * 32;

    for (int t = 0; t < TSTEPS; ++t) {
        float xv[2][4];
#pragma unroll
        for (int cc = 0; cc < 2; ++cc) {
            int cell = tid + cc * 256;
            int r = cell >> 7, hc = cell & 127;
            const float* xp = xproj + ((size_t)(b0 + r) * TSTEPS + t) * G4 + hc;
            xv[cc][0] = xp[0];   xv[cc][1] = xp[128];
            xv[cc][2] = xp[256]; xv[cc][3] = xp[384];
        }

        float acc[4][8];
#pragma unroll
        for (int r = 0; r < 4; ++r)
#pragma unroll
            for (int j = 0; j < 8; ++j) acc[r][j] = 0.0f;

#pragma unroll 8
        for (int kk = 0; kk < 32; ++kk) {
            int k = k0 + kk;
            float h0 = hbuf[k];
            float h1 = hbuf[128 + k];
            float h2 = hbuf[256 + k];
            float h3 = hbuf[384 + k];
#pragma unroll
            for (int j = 0; j < 8; ++j) {
                int g = ggrp + 64 * j;
                float w = (j < 6) ? Wsm[k * 384 + g]
                                  : __ldg(&Wt[k * G4 + g]);
                acc[0][j] += h0 * w;
                acc[1][j] += h1 * w;
                acc[2][j] += h2 * w;
                acc[3][j] += h3 * w;
            }
        }
#pragma unroll
        for (int j = 0; j < 8; ++j) {
            int g = ggrp + 64 * j;
#pragma unroll
            for (int r = 0; r < 4; ++r)
                part[(ksl * 4 + r) * 512 + g] = acc[r][j];
        }
        __syncthreads();

#pragma unroll
        for (int cc = 0; cc < 2; ++cc) {
            int cell = tid + cc * 256;
            int r = cell >> 7, hc = cell & 127;
            float gi = xv[cc][0], gf = xv[cc][1], gg = xv[cc][2], go = xv[cc][3];
#pragma unroll
            for (int s = 0; s < 4; ++s) {
                const float* p = &part[(s * 4 + r) * 512];
                gi += p[hc];
                gf += p[128 + hc];
                gg += p[256 + hc];
                go += p[384 + hc];
            }
            float iv = sigmoidf_(gi);
            float fv = sigmoidf_(gf);
            float gv = tanhf_(gg);
            float ov = sigmoidf_(go);
            float c = fv * creg[cc] + iv * gv;
            creg[cc] = c;
            float h = ov * tanhf_(c);
            hbuf[r * 128 + hc] = h;
            if (LAYER == 0)
                hseq[((size_t)(b0 + r) * TSTEPS + t) * HID + hc] = h;
        }
        __syncthreads();
    }

#pragma unroll
    for (int cc = 0; cc < 2; ++cc) {
        int cell = tid + cc * 256;
        int r = cell >> 7, hc = cell & 127;
        int bi = b0 + r;
        out[OUT_HN_OFF + LAYER * BATCH * HID + bi * HID + hc] = hbuf[r * 128 + hc];
        out[OUT_CN_OFF + LAYER * BATCH * HID + bi * HID + hc] = creg[cc];
    }
}

// ---------------- head: relu(h@fc1^T+b1)@fc2^T+b2 -> softmax ----------------
__global__ __launch_bounds__(256)
void head_kernel(const float* __restrict__ fc1w, const float* __restrict__ fc1b,
                 const float* __restrict__ fc2w, const float* __restrict__ fc2b,
                 float* __restrict__ out) {
    __shared__ float sw1[FC1DIM * HID];
    __shared__ float sw2[NACT * FC1DIM];
    __shared__ float sb1[FC1DIM];
    __shared__ float sb2[NACT];

    for (int i = threadIdx.x; i < FC1DIM * HID; i += 256) sw1[i] = fc1w[i];
    for (int i = threadIdx.x; i < NACT * FC1DIM; i += 256) sw2[i] = fc2w[i];
    if (threadIdx.x < FC1DIM) sb1[threadIdx.x] = fc1b[threadIdx.x];
    if (threadIdx.x < NACT) sb2[threadIdx.x] = fc2b[threadIdx.x];
    __syncthreads();

    int row = blockIdx.x * 256 + threadIdx.x;
    const float* h = out + OUT_HN_OFF + BATCH * HID + row * HID;

    float hid[FC1DIM];
#pragma unroll
    for (int j = 0; j < FC1DIM; ++j) hid[j] = sb1[j];
    for (int k = 0; k < HID; ++k) {
        float hv = h[k];
#pragma unroll
        for (int j = 0; j < FC1DIM; ++j)
            hid[j] += hv * sw1[j * HID + k];
    }
#pragma unroll
    for (int j = 0; j < FC1DIM; ++j) hid[j] = fmaxf(hid[j], 0.0f);

    float logit[NACT];
    float mx = -1e30f;
#pragma unroll
    for (int a = 0; a < NACT; ++a) {
        float l = sb2[a];
#pragma unroll
        for (int j = 0; j < FC1DIM; ++j)
            l += hid[j] * sw2[a * FC1DIM + j];
        logit[a] = l;
        mx = fmaxf(mx, l);
    }
    float sum = 0.0f;
#pragma unroll
    for (int a = 0; a < NACT; ++a) {
        logit[a] = __expf(logit[a] - mx);
        sum += logit[a];
    }
    float inv = 1.0f / sum;
#pragma unroll
    for (int a = 0; a < NACT; ++a)
        out[row * NACT + a] = logit[a] * inv;
}

// ---------------- launch ----------------
extern "C" void kernel_launch(void* const* d_in, const int* in_sizes, int n_in,
                              void* d_out, int out_size) {
    (void)in_sizes; (void)n_in; (void)out_size;
    const float* x     = (const float*)d_in[0];
    const float* Wih0  = (const float*)d_in[1];
    const float* Whh0  = (const float*)d_in[2];
    const float* bih0  = (const float*)d_in[3];
    const float* bhh0  = (const float*)d_in[4];
    const float* Wih1  = (const float*)d_in[5];
    const float* Whh1  = (const float*)d_in[6];
    const float* bih1  = (const float*)d_in[7];
    const float* bhh1  = (const float*)d_in[8];
    const float* fc1w  = (const float*)d_in[9];
    const float* fc1b  = (const float*)d_in[10];
    const float* fc2w  = (const float*)d_in[11];
    const float* fc2b  = (const float*)d_in[12];
    float* out = (float*)d_out;

    float* xproj = nullptr;
    float* hseq  = nullptr;
    __nv_bfloat16 *w0hi = nullptr, *w0lo = nullptr, *w1hi = nullptr, *w1lo = nullptr;
    cudaGetSymbolAddress((void**)&xproj, g_xproj);
    cudaGetSymbolAddress((void**)&hseq, g_hseq);
    cudaGetSymbolAddress((void**)&w0hi, g_Wih0_hi);
    cudaGetSymbolAddress((void**)&w0lo, g_Wih0_lo);
    cudaGetSymbolAddress((void**)&w1hi, g_Wih1_hi);
    cudaGetSymbolAddress((void**)&w1lo, g_Wih1_lo);

    cudaFuncSetAttribute(lstm_kernel<0>,
                         cudaFuncAttributeMaxDynamicSharedMemorySize,
                         LSTM_SMEM_FLOATS * 4);
    cudaFuncSetAttribute(lstm_kernel<1>,
                         cudaFuncAttributeMaxDynamicSharedMemorySize,
                         LSTM_SMEM_FLOATS * 4);

    // 1) weight prep: transpose Whh, split Wih to bf16 hi/lo
    prep_weights_kernel<<<1024, 256>>>(Whh0, Whh1, Wih0, Wih1);

    // 2) x_proj0 = x @ Wih0^T + bih0 + bhh0  (mma.sync bf16 hi/lo)
    gemm_mma_kernel<INPUT><<<dim3(4, MROWS / 128), 256>>>(x, w0hi, w0lo, bih0, bhh0, xproj);

    // 3) layer-0 recurrence
    lstm_kernel<0><<<BATCH / 4, 256, LSTM_SMEM_FLOATS * 4>>>(xproj, hseq, out);

    // 4) x_proj1 = h0_seq @ Wih1^T + bih1 + bhh1
    gemm_mma_kernel<HID><<<dim3(4, MROWS / 128), 256>>>(hseq, w1hi, w1lo, bih1, bhh1, xproj);

    // 5) layer-1 recurrence
    lstm_kernel<1><<<BATCH / 4, 256, LSTM_SMEM_FLOATS * 4>>>(xproj, nullptr, out);

    // 6) head
    head_kernel<<<2, 256>>>(fc1w, fc1b, fc2w, fc2b, out);
}

// round 7
// speedup vs baseline: 1.5055x; 1.1196x over previous
// R7: byte-identical resubmit of R6 (ffma2 LSTM + cp.async double-buffered
// bf16 GEMM). R4->R5 precedent: opaque "container failed twice" is a broker
// flake; real kernel errors reproduce with diagnostics on resubmit.
#include <cuda_runtime.h>
#include <cuda_bf16.h>
#include <cstdint>
#include <math.h>

#define BATCH 512
#define TSTEPS 256
#define INPUT 512
#define HID 128
#define G4 512          // 4*HID
#define FC1DIM 64
#define NACT 10
#define MROWS (BATCH*TSTEPS)   // 131072

typedef unsigned long long u64t;

// ---------------- scratch (static device memory; no allocs) ----------------
__device__ float g_xproj[(size_t)MROWS * G4];        // 256 MB, reused by both layers
__device__ float g_Wt[2][HID * G4];                  // Whh transposed to [k][g]
__device__ __nv_bfloat16 g_x_hi[(size_t)MROWS * INPUT];   // 128 MB
__device__ __nv_bfloat16 g_x_lo[(size_t)MROWS * INPUT];   // 128 MB
__device__ __nv_bfloat16 g_h_hi[(size_t)MROWS * HID];     // 32 MB (layer0 h seq)
__device__ __nv_bfloat16 g_h_lo[(size_t)MROWS * HID];     // 32 MB
__device__ __nv_bfloat16 g_Wih0_hi[G4 * INPUT];
__device__ __nv_bfloat16 g_Wih0_lo[G4 * INPUT];
__device__ __nv_bfloat16 g_Wih1_hi[G4 * HID];
__device__ __nv_bfloat16 g_Wih1_lo[G4 * HID];

// output layout in d_out (float32):
//   probs [512*10]  | h_n [2*512*128] | c_n [2*512*128]
#define OUT_HN_OFF   (BATCH*NACT)                     // 5120
#define OUT_CN_OFF   (OUT_HN_OFF + 2*BATCH*HID)      // 136192

// ---------------- helpers ----------------
__device__ __forceinline__ float sigmoidf_(float x) {
    return 1.0f / (1.0f + __expf(-x));
}
__device__ __forceinline__ float tanhf_(float x) {
    return 1.0f - 2.0f / (__expf(2.0f * x) + 1.0f);
}
__device__ __forceinline__ uint32_t smem_u32(const void* p) {
    uint32_t a;
    asm("{ .reg .u64 t; cvta.to.shared.u64 t, %1; cvt.u32.u64 %0, t; }"
        : "=r"(a) : "l"(p));
    return a;
}
__device__ __forceinline__ uint32_t pack_bf16(float a, float b) {
    __nv_bfloat162 t = __floats2bfloat162_rn(a, b);
    return *reinterpret_cast<uint32_t*>(&t);
}
__device__ __forceinline__ void ldsm_x4(uint32_t& r0, uint32_t& r1,
                                        uint32_t& r2, uint32_t& r3,
                                        uint32_t addr) {
    asm volatile("ldmatrix.sync.aligned.m8n8.x4.shared.b16 {%0,%1,%2,%3}, [%4];"
                 : "=r"(r0), "=r"(r1), "=r"(r2), "=r"(r3) : "r"(addr));
}
__device__ __forceinline__ void mma16816(float* c, uint32_t a0, uint32_t a1,
                                         uint32_t a2, uint32_t a3,
                                         uint32_t b0, uint32_t b1) {
    asm volatile(
        "mma.sync.aligned.m16n8k16.row.col.f32.bf16.bf16.f32 "
        "{%0,%1,%2,%3}, {%4,%5,%6,%7}, {%8,%9}, {%0,%1,%2,%3};"
        : "+f"(c[0]), "+f"(c[1]), "+f"(c[2]), "+f"(c[3])
        : "r"(a0), "r"(a1), "r"(a2), "r"(a3), "r"(b0), "r"(b1));
}
// packed fp32x2 FMA (Blackwell; PTX ISA 8.6, target sm_100)
__device__ __forceinline__ void ffma2(u64t& acc, u64t a, u64t b) {
    asm("fma.rn.f32x2 %0, %1, %2, %0;" : "+l"(acc) : "l"(a), "l"(b));
}
__device__ __forceinline__ u64t bcast2(float x) {
    u64t r;
    asm("mov.b64 %0, {%1, %1};" : "=l"(r) : "f"(x));
    return r;
}
__device__ __forceinline__ void cp_async16(uint32_t dst, const void* src) {
    asm volatile("cp.async.cg.shared.global [%0], [%1], 16;"
                 :: "r"(dst), "l"(src));
}
__device__ __forceinline__ void cp_commit() {
    asm volatile("cp.async.commit_group;");
}
template<int N>
__device__ __forceinline__ void cp_wait() {
    asm volatile("cp.async.wait_group %0;" :: "n"(N));
}

// ---------------- weight prep: transpose Whh + split Wih to bf16 hi/lo ----
__global__ void prep_weights_kernel(const float* __restrict__ whh0,
                                    const float* __restrict__ whh1,
                                    const float* __restrict__ wih0,
                                    const float* __restrict__ wih1) {
    int idx = blockIdx.x * 256 + threadIdx.x;   // up to 262144
    if (idx < 65536) {
        int k = idx >> 9;
        int g = idx & 511;
        g_Wt[0][k * G4 + g] = whh0[g * HID + k];
        g_Wt[1][k * G4 + g] = whh1[g * HID + k];
    }
    if (idx < G4 * INPUT) {
        float v = wih0[idx];
        __nv_bfloat16 h = __float2bfloat16(v);
        g_Wih0_hi[idx] = h;
        g_Wih0_lo[idx] = __float2bfloat16(v - __bfloat162float(h));
    }
    if (idx < G4 * HID) {
        float v = wih1[idx];
        __nv_bfloat16 h = __float2bfloat16(v);
        g_Wih1_hi[idx] = h;
        g_Wih1_lo[idx] = __float2bfloat16(v - __bfloat162float(h));
    }
}

// ---------------- split x into bf16 hi/lo (once) ----------------
__global__ void split_x_kernel(const float* __restrict__ x) {
    size_t i4 = (size_t)blockIdx.x * 256 + threadIdx.x;   // float4 index
    float4 v = *reinterpret_cast<const float4*>(&x[i4 * 4]);
    float hx = __bfloat162float(__float2bfloat16(v.x));
    float hy = __bfloat162float(__float2bfloat16(v.y));
    float hz = __bfloat162float(__float2bfloat16(v.z));
    float hw = __bfloat162float(__float2bfloat16(v.w));
    *reinterpret_cast<uint2*>(&g_x_hi[i4 * 4]) =
        make_uint2(pack_bf16(v.x, v.y), pack_bf16(v.z, v.w));
    *reinterpret_cast<uint2*>(&g_x_lo[i4 * 4]) =
        make_uint2(pack_bf16(v.x - hx, v.y - hy), pack_bf16(v.z - hz, v.w - hw));
}

// ---------------- mma.sync bf16 GEMM (cp.async double-buffered) ----------
// C[M][512] = A[M][K] @ W[512][K]^T + bias ; A,W pre-split bf16 hi/lo.
// CTA tile 128x128, BK=32, 256 threads, warp tile 64x32, 3-pass hi/lo.
#define SSTR 40
#define STG_ELEMS (4 * 128 * SSTR)   // 20480 bf16 per stage
#define T_AHI 0
#define T_ALO (128*SSTR)
#define T_WHI (2*128*SSTR)
#define T_WLO (3*128*SSTR)
#define GEMM_SMEM (2 * STG_ELEMS * 2)   // 81920 B

template<int K>
__global__ __launch_bounds__(256)
void gemm_mma_kernel(const __nv_bfloat16* __restrict__ Ahi,
                     const __nv_bfloat16* __restrict__ Alo,
                     const __nv_bfloat16* __restrict__ Whi,
                     const __nv_bfloat16* __restrict__ Wlo,
                     const float* __restrict__ bih,
                     const float* __restrict__ bhh,
                     float* __restrict__ C) {
    extern __shared__ __align__(16) __nv_bfloat16 smg[];

    const int tid = threadIdx.x;
    const int wid = tid >> 5;
    const int lane = tid & 31;
    const int wm = wid & 1;
    const int wn = wid >> 1;
    const int m0 = blockIdx.y * 128;
    const int n0 = blockIdx.x * 128;
    constexpr int NCH = K / 32;
    const uint32_t smb = smem_u32(smg);

    // per-thread load coords: 2 chunks of 16B per tile per stage
    const int lr0 = tid >> 2;                 // rows 0..63
    const int lc  = (tid & 3) * 8;            // bf16 col offset 0,8,16,24

    // load one stage (4 tiles x 128 rows x 32 cols bf16)
    auto load_stage = [&](int st, int kc) {
        uint32_t base = (uint32_t)(st * STG_ELEMS);
#pragma unroll
        for (int q = 0; q < 2; ++q) {
            int r = lr0 + q * 64;
            uint32_t so = base + r * SSTR + lc;
            cp_async16(smb + (so + T_AHI) * 2, &Ahi[(size_t)(m0 + r) * K + kc + lc]);
            cp_async16(smb + (so + T_ALO) * 2, &Alo[(size_t)(m0 + r) * K + kc + lc]);
            cp_async16(smb + (so + T_WHI) * 2, &Whi[(size_t)(n0 + r) * K + kc + lc]);
            cp_async16(smb + (so + T_WLO) * 2, &Wlo[(size_t)(n0 + r) * K + kc + lc]);
        }
    };

    float acc[4][4][4];
#pragma unroll
    for (int mf = 0; mf < 4; ++mf)
#pragma unroll
        for (int nf = 0; nf < 4; ++nf)
#pragma unroll
            for (int i = 0; i < 4; ++i) acc[mf][nf][i] = 0.0f;

    load_stage(0, 0);
    cp_commit();
    if (NCH > 1) load_stage(1, 32);
    cp_commit();

    const int a_row = (lane & 15);
    const int a_kofs = (lane >> 4) * 8;
    const int b_row = (lane & 7) + ((lane >> 4) & 1) * 8;
    const int b_kofs = ((lane >> 3) & 1) * 8;

    for (int ch = 0; ch < NCH; ++ch) {
        cp_wait<1>();
        __syncthreads();
        const uint32_t sb = smb + (uint32_t)((ch & 1) * STG_ELEMS) * 2;

#pragma unroll
        for (int kk = 0; kk < 32; kk += 16) {
            uint32_t bh[8], bl[8];
#pragma unroll
            for (int nfp = 0; nfp < 2; ++nfp) {
                int row = wn * 32 + nfp * 16 + b_row;
                uint32_t off = (uint32_t)(row * SSTR + kk + b_kofs) * 2;
                ldsm_x4(bh[nfp * 4 + 0], bh[nfp * 4 + 1],
                        bh[nfp * 4 + 2], bh[nfp * 4 + 3], sb + T_WHI * 2 + off);
                ldsm_x4(bl[nfp * 4 + 0], bl[nfp * 4 + 1],
                        bl[nfp * 4 + 2], bl[nfp * 4 + 3], sb + T_WLO * 2 + off);
            }
#pragma unroll
            for (int mf = 0; mf < 4; ++mf) {
                int row = wm * 64 + mf * 16 + a_row;
                uint32_t off = (uint32_t)(row * SSTR + kk + a_kofs) * 2;
                uint32_t ah0, ah1, ah2, ah3, al0, al1, al2, al3;
                ldsm_x4(ah0, ah1, ah2, ah3, sb + T_AHI * 2 + off);
                ldsm_x4(al0, al1, al2, al3, sb + T_ALO * 2 + off);
#pragma unroll
                for (int nf = 0; nf < 4; ++nf) {
                    uint32_t b0h = bh[(nf >> 1) * 4 + (nf & 1) * 2 + 0];
                    uint32_t b1h = bh[(nf >> 1) * 4 + (nf & 1) * 2 + 1];
                    uint32_t b0l = bl[(nf >> 1) * 4 + (nf & 1) * 2 + 0];
                    uint32_t b1l = bl[(nf >> 1) * 4 + (nf & 1) * 2 + 1];
                    mma16816(acc[mf][nf], ah0, ah1, ah2, ah3, b0h, b1h);
                    mma16816(acc[mf][nf], ah0, ah1, ah2, ah3, b0l, b1l);
                    mma16816(acc[mf][nf], al0, al1, al2, al3, b0h, b1h);
                }
            }
        }
        __syncthreads();
        if (ch + 2 < NCH) load_stage(ch & 1, (ch + 2) * 32);
        cp_commit();
    }

    // ---- epilogue: bias + store
    const int mbase = m0 + wm * 64;
    const int nbase = n0 + wn * 32;
    float bs0[4], bs1[4];
#pragma unroll
    for (int nf = 0; nf < 4; ++nf) {
        int c = nbase + nf * 8 + (lane & 3) * 2;
        bs0[nf] = bih[c] + bhh[c];
        bs1[nf] = bih[c + 1] + bhh[c + 1];
    }
#pragma unroll
    for (int mf = 0; mf < 4; ++mf) {
        int row0 = mbase + mf * 16 + (lane >> 2);
#pragma unroll
        for (int nf = 0; nf < 4; ++nf) {
            int col = nbase + nf * 8 + (lane & 3) * 2;
            float2 v0 = make_float2(acc[mf][nf][0] + bs0[nf],
                                    acc[mf][nf][1] + bs1[nf]);
            float2 v1 = make_float2(acc[mf][nf][2] + bs0[nf],
                                    acc[mf][nf][3] + bs1[nf]);
            *reinterpret_cast<float2*>(&C[(size_t)row0 * G4 + col]) = v0;
            *reinterpret_cast<float2*>(&C[(size_t)(row0 + 8) * G4 + col]) = v1;
        }
    }
}

// ---------------- LSTM recurrence: packed f32x2 FMA inner loop ----------
// Thread (ksl=tid>>6, ggrp=tid&63) handles gate PAIRS g = 2*ggrp + 128*jp,
// jp=0..2 from smem (i,f,g gates), jp=3 (o gate) streamed from L2.
#define LSTM_SMEM_FLOATS (128*384 + 4*4*512 + 4*128)   // 231424 B

template<int LAYER>
__global__ __launch_bounds__(256, 1)
void lstm_kernel(const float* __restrict__ xproj,
                 float* __restrict__ out) {
    extern __shared__ float smemf[];
    float* Wsm  = smemf;                      // [128][384] i,f,g gate weights
    float* part = smemf + 128 * 384;          // [16][512]
    float* hbuf = part + 4 * 4 * 512;         // [4][128]

    const float* Wt = g_Wt[LAYER];            // [128][512]
    const int tid = threadIdx.x;
    const int b0 = blockIdx.x * 4;

    for (int i = tid; i < 128 * 384 / 4; i += 256) {
        int k = i / 96;
        int gc4 = (i % 96) * 4;
        *(float4*)&Wsm[k * 384 + gc4] = *(const float4*)&Wt[k * G4 + gc4];
    }
    for (int i = tid; i < 4 * 128; i += 256) hbuf[i] = 0.0f;
    float creg[2] = {0.0f, 0.0f};
    __syncthreads();

    const int ksl  = tid >> 6;
    const int ggrp = tid & 63;
    const int k0   = ksl * 32;
    const int g2   = ggrp * 2;

    for (int t = 0; t < TSTEPS; ++t) {
        float xv[2][4];
#pragma unroll
        for (int cc = 0; cc < 2; ++cc) {
            int cell = tid + cc * 256;
            int r = cell >> 7, hc = cell & 127;
            const float* xp = xproj + ((size_t)(b0 + r) * TSTEPS + t) * G4 + hc;
            xv[cc][0] = xp[0];   xv[cc][1] = xp[128];
            xv[cc][2] = xp[256]; xv[cc][3] = xp[384];
        }

        u64t acc2[4][4];
#pragma unroll
        for (int r = 0; r < 4; ++r)
#pragma unroll
            for (int jp = 0; jp < 4; ++jp) acc2[r][jp] = 0ull;

#pragma unroll 8
        for (int kk = 0; kk < 32; ++kk) {
            int k = k0 + kk;
            u64t h2[4];
            h2[0] = bcast2(hbuf[k]);
            h2[1] = bcast2(hbuf[128 + k]);
            h2[2] = bcast2(hbuf[256 + k]);
            h2[3] = bcast2(hbuf[384 + k]);
            u64t w0 = *(const u64t*)&Wsm[k * 384 + g2];
            u64t w1 = *(const u64t*)&Wsm[k * 384 + 128 + g2];
            u64t w2 = *(const u64t*)&Wsm[k * 384 + 256 + g2];
            u64t w3 = __ldg((const u64t*)&Wt[k * G4 + 384 + g2]);
#pragma unroll
            for (int r = 0; r < 4; ++r) {
                ffma2(acc2[r][0], h2[r], w0);
                ffma2(acc2[r][1], h2[r], w1);
                ffma2(acc2[r][2], h2[r], w2);
                ffma2(acc2[r][3], h2[r], w3);
            }
        }
#pragma unroll
        for (int jp = 0; jp < 4; ++jp) {
            int g = g2 + 128 * jp;
#pragma unroll
            for (int r = 0; r < 4; ++r)
                *(u64t*)&part[(ksl * 4 + r) * 512 + g] = acc2[r][jp];
        }
        __syncthreads();

#pragma unroll
        for (int cc = 0; cc < 2; ++cc) {
            int cell = tid + cc * 256;
            int r = cell >> 7, hc = cell & 127;
            float gi = xv[cc][0], gf = xv[cc][1], gg = xv[cc][2], go = xv[cc][3];
#pragma unroll
            for (int s = 0; s < 4; ++s) {
                const float* p = &part[(s * 4 + r) * 512];
                gi += p[hc];
                gf += p[128 + hc];
                gg += p[256 + hc];
                go += p[384 + hc];
            }
            float iv = sigmoidf_(gi);
            float fv = sigmoidf_(gf);
            float gv = tanhf_(gg);
            float ov = sigmoidf_(go);
            float c = fv * creg[cc] + iv * gv;
            creg[cc] = c;
            float h = ov * tanhf_(c);
            hbuf[r * 128 + hc] = h;
            if (LAYER == 0) {
                size_t o = ((size_t)(b0 + r) * TSTEPS + t) * HID + hc;
                __nv_bfloat16 hb = __float2bfloat16(h);
                g_h_hi[o] = hb;
                g_h_lo[o] = __float2bfloat16(h - __bfloat162float(hb));
            }
        }
        __syncthreads();
    }

#pragma unroll
    for (int cc = 0; cc < 2; ++cc) {
        int cell = tid + cc * 256;
        int r = cell >> 7, hc = cell & 127;
        int bi = b0 + r;
        out[OUT_HN_OFF + LAYER * BATCH * HID + bi * HID + hc] = hbuf[r * 128 + hc];
        out[OUT_CN_OFF + LAYER * BATCH * HID + bi * HID + hc] = creg[cc];
    }
}

// ---------------- head: relu(h@fc1^T+b1)@fc2^T+b2 -> softmax ----------------
__global__ __launch_bounds__(256)
void head_kernel(const float* __restrict__ fc1w, const float* __restrict__ fc1b,
                 const float* __restrict__ fc2w, const float* __restrict__ fc2b,
                 float* __restrict__ out) {
    __shared__ float sw1[FC1DIM * HID];
    __shared__ float sw2[NACT * FC1DIM];
    __shared__ float sb1[FC1DIM];
    __shared__ float sb2[NACT];

    for (int i = threadIdx.x; i < FC1DIM * HID; i += 256) sw1[i] = fc1w[i];
    for (int i = threadIdx.x; i < NACT * FC1DIM; i += 256) sw2[i] = fc2w[i];
    if (threadIdx.x < FC1DIM) sb1[threadIdx.x] = fc1b[threadIdx.x];
    if (threadIdx.x < NACT) sb2[threadIdx.x] = fc2b[threadIdx.x];
    __syncthreads();

    int row = blockIdx.x * 256 + threadIdx.x;
    const float* h = out + OUT_HN_OFF + BATCH * HID + row * HID;

    float hid[FC1DIM];
#pragma unroll
    for (int j = 0; j < FC1DIM; ++j) hid[j] = sb1[j];
    for (int k = 0; k < HID; ++k) {
        float hv = h[k];
#pragma unroll
        for (int j = 0; j < FC1DIM; ++j)
            hid[j] += hv * sw1[j * HID + k];
    }
#pragma unroll
    for (int j = 0; j < FC1DIM; ++j) hid[j] = fmaxf(hid[j], 0.0f);

    float logit[NACT];
    float mx = -1e30f;
#pragma unroll
    for (int a = 0; a < NACT; ++a) {
        float l = sb2[a];
#pragma unroll
        for (int j = 0; j < FC1DIM; ++j)
            l += hid[j] * sw2[a * FC1DIM + j];
        logit[a] = l;
        mx = fmaxf(mx, l);
    }
    float sum = 0.0f;
#pragma unroll
    for (int a = 0; a < NACT; ++a) {
        logit[a] = __expf(logit[a] - mx);
        sum += logit[a];
    }
    float inv = 1.0f / sum;
#pragma unroll
    for (int a = 0; a < NACT; ++a)
        out[row * NACT + a] = logit[a] * inv;
}

// ---------------- launch ----------------
extern "C" void kernel_launch(void* const* d_in, const int* in_sizes, int n_in,
                              void* d_out, int out_size) {
    (void)in_sizes; (void)n_in; (void)out_size;
    const float* x     = (const float*)d_in[0];
    const float* Wih0  = (const float*)d_in[1];
    const float* Whh0  = (const float*)d_in[2];
    const float* bih0  = (const float*)d_in[3];
    const float* bhh0  = (const float*)d_in[4];
    const float* Wih1  = (const float*)d_in[5];
    const float* Whh1  = (const float*)d_in[6];
    const float* bih1  = (const float*)d_in[7];
    const float* bhh1  = (const float*)d_in[8];
    const float* fc1w  = (const float*)d_in[9];
    const float* fc1b  = (const float*)d_in[10];
    const float* fc2w  = (const float*)d_in[11];
    const float* fc2b  = (const float*)d_in[12];
    float* out = (float*)d_out;

    float* xproj = nullptr;
    __nv_bfloat16 *xhi, *xlo, *hhi, *hlo, *w0hi, *w0lo, *w1hi, *w1lo;
    cudaGetSymbolAddress((void**)&xproj, g_xproj);
    cudaGetSymbolAddress((void**)&xhi, g_x_hi);
    cudaGetSymbolAddress((void**)&xlo, g_x_lo);
    cudaGetSymbolAddress((void**)&hhi, g_h_hi);
    cudaGetSymbolAddress((void**)&hlo, g_h_lo);
    cudaGetSymbolAddress((void**)&w0hi, g_Wih0_hi);
    cudaGetSymbolAddress((void**)&w0lo, g_Wih0_lo);
    cudaGetSymbolAddress((void**)&w1hi, g_Wih1_hi);
    cudaGetSymbolAddress((void**)&w1lo, g_Wih1_lo);

    cudaFuncSetAttribute(lstm_kernel<0>,
                         cudaFuncAttributeMaxDynamicSharedMemorySize,
                         LSTM_SMEM_FLOATS * 4);
    cudaFuncSetAttribute(lstm_kernel<1>,
                         cudaFuncAttributeMaxDynamicSharedMemorySize,
                         LSTM_SMEM_FLOATS * 4);
    cudaFuncSetAttribute(gemm_mma_kernel<INPUT>,
                         cudaFuncAttributeMaxDynamicSharedMemorySize, GEMM_SMEM);
    cudaFuncSetAttribute(gemm_mma_kernel<HID>,
                         cudaFuncAttributeMaxDynamicSharedMemorySize, GEMM_SMEM);

    // 1) weight prep + x split
    prep_weights_kernel<<<1024, 256>>>(Whh0, Whh1, Wih0, Wih1);
    split_x_kernel<<<MROWS * INPUT / 4 / 256, 256>>>(x);

    // 2) x_proj0 = x @ Wih0^T + bias (tensor cores, double-buffered)
    gemm_mma_kernel<INPUT><<<dim3(4, MROWS / 128), 256, GEMM_SMEM>>>(
        xhi, xlo, w0hi, w0lo, bih0, bhh0, xproj);

    // 3) layer-0 recurrence (writes h seq as bf16 hi/lo)
    lstm_kernel<0><<<BATCH / 4, 256, LSTM_SMEM_FLOATS * 4>>>(xproj, out);

    // 4) x_proj1 = h0_seq @ Wih1^T + bias
    gemm_mma_kernel<HID><<<dim3(4, MROWS / 128), 256, GEMM_SMEM>>>(
        hhi, hlo, w1hi, w1lo, bih1, bhh1, xproj);

    // 5) layer-1 recurrence
    lstm_kernel<1><<<BATCH / 4, 256, LSTM_SMEM_FLOATS * 4>>>(xproj, out);

    // 6) head
    head_kernel<<<2, 256>>>(fc1w, fc1b, fc2w, fc2b, out);
}

// round 8
// speedup vs baseline: 1.7529x; 1.1643x over previous
#include <cuda_runtime.h>
#include <cuda_bf16.h>
#include <cstdint>
#include <math.h>

#define BATCH 512
#define TSTEPS 256
#define INPUT 512
#define HID 128
#define G4 512          // 4*HID
#define FC1DIM 64
#define NACT 10
#define MROWS (BATCH*TSTEPS)   // 131072

typedef unsigned long long u64t;

// ---------------- scratch (static device memory; no allocs) ----------------
__device__ float g_xproj[(size_t)MROWS * G4];        // 256 MB, reused by both layers
__device__ float g_Wt[2][HID * G4];                  // Whh transposed to [k][g]
__device__ __nv_bfloat16 g_x_hi[(size_t)MROWS * INPUT];   // 128 MB
__device__ __nv_bfloat16 g_x_lo[(size_t)MROWS * INPUT];   // 128 MB
__device__ __nv_bfloat16 g_h_hi[(size_t)MROWS * HID];     // 32 MB (layer0 h seq)
__device__ __nv_bfloat16 g_h_lo[(size_t)MROWS * HID];     // 32 MB
__device__ __nv_bfloat16 g_Wih0_hi[G4 * INPUT];
__device__ __nv_bfloat16 g_Wih0_lo[G4 * INPUT];
__device__ __nv_bfloat16 g_Wih1_hi[G4 * HID];
__device__ __nv_bfloat16 g_Wih1_lo[G4 * HID];

// output layout in d_out (float32):
//   probs [512*10]  | h_n [2*512*128] | c_n [2*512*128]
#define OUT_HN_OFF   (BATCH*NACT)                     // 5120
#define OUT_CN_OFF   (OUT_HN_OFF + 2*BATCH*HID)      // 136192

// ---------------- helpers ----------------
__device__ __forceinline__ float sigmoidf_(float x) {
    return 1.0f / (1.0f + __expf(-x));
}
__device__ __forceinline__ float tanhf_(float x) {
    return 1.0f - 2.0f / (__expf(2.0f * x) + 1.0f);
}
__device__ __forceinline__ uint32_t smem_u32(const void* p) {
    uint32_t a;
    asm("{ .reg .u64 t; cvta.to.shared.u64 t, %1; cvt.u32.u64 %0, t; }"
        : "=r"(a) : "l"(p));
    return a;
}
__device__ __forceinline__ uint32_t pack_bf16(float a, float b) {
    __nv_bfloat162 t = __floats2bfloat162_rn(a, b);
    return *reinterpret_cast<uint32_t*>(&t);
}
__device__ __forceinline__ void ldsm_x4(uint32_t& r0, uint32_t& r1,
                                        uint32_t& r2, uint32_t& r3,
                                        uint32_t addr) {
    asm volatile("ldmatrix.sync.aligned.m8n8.x4.shared.b16 {%0,%1,%2,%3}, [%4];"
                 : "=r"(r0), "=r"(r1), "=r"(r2), "=r"(r3) : "r"(addr));
}
__device__ __forceinline__ void mma16816(float* c, uint32_t a0, uint32_t a1,
                                         uint32_t a2, uint32_t a3,
                                         uint32_t b0, uint32_t b1) {
    asm volatile(
        "mma.sync.aligned.m16n8k16.row.col.f32.bf16.bf16.f32 "
        "{%0,%1,%2,%3}, {%4,%5,%6,%7}, {%8,%9}, {%0,%1,%2,%3};"
        : "+f"(c[0]), "+f"(c[1]), "+f"(c[2]), "+f"(c[3])
        : "r"(a0), "r"(a1), "r"(a2), "r"(a3), "r"(b0), "r"(b1));
}
// packed fp32x2 FMA (Blackwell; PTX ISA 8.6, target sm_100)
__device__ __forceinline__ void ffma2(u64t& acc, u64t a, u64t b) {
    asm("fma.rn.f32x2 %0, %1, %2, %0;" : "+l"(acc) : "l"(a), "l"(b));
}
__device__ __forceinline__ u64t bcast2(float x) {
    u64t r;
    asm("mov.b64 %0, {%1, %1};" : "=l"(r) : "f"(x));
    return r;
}
__device__ __forceinline__ float lo_f(u64t v) {
    return __uint_as_float((uint32_t)(v & 0xffffffffull));
}
__device__ __forceinline__ float hi_f(u64t v) {
    return __uint_as_float((uint32_t)(v >> 32));
}
__device__ __forceinline__ void cp_async16(uint32_t dst, const void* src) {
    asm volatile("cp.async.cg.shared.global [%0], [%1], 16;"
                 :: "r"(dst), "l"(src));
}
__device__ __forceinline__ void cp_commit() {
    asm volatile("cp.async.commit_group;");
}
template<int N>
__device__ __forceinline__ void cp_wait() {
    asm volatile("cp.async.wait_group %0;" :: "n"(N));
}

// ---------------- weight prep: transpose Whh + split Wih to bf16 hi/lo ----
__global__ void prep_weights_kernel(const float* __restrict__ whh0,
                                    const float* __restrict__ whh1,
                                    const float* __restrict__ wih0,
                                    const float* __restrict__ wih1) {
    int idx = blockIdx.x * 256 + threadIdx.x;   // up to 262144
    if (idx < 65536) {
        int k = idx >> 9;
        int g = idx & 511;
        g_Wt[0][k * G4 + g] = whh0[g * HID + k];
        g_Wt[1][k * G4 + g] = whh1[g * HID + k];
    }
    if (idx < G4 * INPUT) {
        float v = wih0[idx];
        __nv_bfloat16 h = __float2bfloat16(v);
        g_Wih0_hi[idx] = h;
        g_Wih0_lo[idx] = __float2bfloat16(v - __bfloat162float(h));
    }
    if (idx < G4 * HID) {
        float v = wih1[idx];
        __nv_bfloat16 h = __float2bfloat16(v);
        g_Wih1_hi[idx] = h;
        g_Wih1_lo[idx] = __float2bfloat16(v - __bfloat162float(h));
    }
}

// ---------------- split x into bf16 hi/lo (once) ----------------
__global__ void split_x_kernel(const float* __restrict__ x) {
    size_t i4 = (size_t)blockIdx.x * 256 + threadIdx.x;   // float4 index
    float4 v = *reinterpret_cast<const float4*>(&x[i4 * 4]);
    float hx = __bfloat162float(__float2bfloat16(v.x));
    float hy = __bfloat162float(__float2bfloat16(v.y));
    float hz = __bfloat162float(__float2bfloat16(v.z));
    float hw = __bfloat162float(__float2bfloat16(v.w));
    *reinterpret_cast<uint2*>(&g_x_hi[i4 * 4]) =
        make_uint2(pack_bf16(v.x, v.y), pack_bf16(v.z, v.w));
    *reinterpret_cast<uint2*>(&g_x_lo[i4 * 4]) =
        make_uint2(pack_bf16(v.x - hx, v.y - hy), pack_bf16(v.z - hz, v.w - hw));
}

// ---------------- mma.sync bf16 GEMM (cp.async double-buffered) ----------
// (unchanged from R7)
#define SSTR 40
#define STG_ELEMS (4 * 128 * SSTR)   // 20480 bf16 per stage
#define T_AHI 0
#define T_ALO (128*SSTR)
#define T_WHI (2*128*SSTR)
#define T_WLO (3*128*SSTR)
#define GEMM_SMEM (2 * STG_ELEMS * 2)   // 81920 B

template<int K>
__global__ __launch_bounds__(256)
void gemm_mma_kernel(const __nv_bfloat16* __restrict__ Ahi,
                     const __nv_bfloat16* __restrict__ Alo,
                     const __nv_bfloat16* __restrict__ Whi,
                     const __nv_bfloat16* __restrict__ Wlo,
                     const float* __restrict__ bih,
                     const float* __restrict__ bhh,
                     float* __restrict__ C) {
    extern __shared__ __align__(16) __nv_bfloat16 smg[];

    const int tid = threadIdx.x;
    const int wid = tid >> 5;
    const int lane = tid & 31;
    const int wm = wid & 1;
    const int wn = wid >> 1;
    const int m0 = blockIdx.y * 128;
    const int n0 = blockIdx.x * 128;
    constexpr int NCH = K / 32;
    const uint32_t smb = smem_u32(smg);

    const int lr0 = tid >> 2;
    const int lc  = (tid & 3) * 8;

    auto load_stage = [&](int st, int kc) {
        uint32_t base = (uint32_t)(st * STG_ELEMS);
#pragma unroll
        for (int q = 0; q < 2; ++q) {
            int r = lr0 + q * 64;
            uint32_t so = base + r * SSTR + lc;
            cp_async16(smb + (so + T_AHI) * 2, &Ahi[(size_t)(m0 + r) * K + kc + lc]);
            cp_async16(smb + (so + T_ALO) * 2, &Alo[(size_t)(m0 + r) * K + kc + lc]);
            cp_async16(smb + (so + T_WHI) * 2, &Whi[(size_t)(n0 + r) * K + kc + lc]);
            cp_async16(smb + (so + T_WLO) * 2, &Wlo[(size_t)(n0 + r) * K + kc + lc]);
        }
    };

    float acc[4][4][4];
#pragma unroll
    for (int mf = 0; mf < 4; ++mf)
#pragma unroll
        for (int nf = 0; nf < 4; ++nf)
#pragma unroll
            for (int i = 0; i < 4; ++i) acc[mf][nf][i] = 0.0f;

    load_stage(0, 0);
    cp_commit();
    if (NCH > 1) load_stage(1, 32);
    cp_commit();

    const int a_row = (lane & 15);
    const int a_kofs = (lane >> 4) * 8;
    const int b_row = (lane & 7) + ((lane >> 4) & 1) * 8;
    const int b_kofs = ((lane >> 3) & 1) * 8;

    for (int ch = 0; ch < NCH; ++ch) {
        cp_wait<1>();
        __syncthreads();
        const uint32_t sb = smb + (uint32_t)((ch & 1) * STG_ELEMS) * 2;

#pragma unroll
        for (int kk = 0; kk < 32; kk += 16) {
            uint32_t bh[8], bl[8];
#pragma unroll
            for (int nfp = 0; nfp < 2; ++nfp) {
                int row = wn * 32 + nfp * 16 + b_row;
                uint32_t off = (uint32_t)(row * SSTR + kk + b_kofs) * 2;
                ldsm_x4(bh[nfp * 4 + 0], bh[nfp * 4 + 1],
                        bh[nfp * 4 + 2], bh[nfp * 4 + 3], sb + T_WHI * 2 + off);
                ldsm_x4(bl[nfp * 4 + 0], bl[nfp * 4 + 1],
                        bl[nfp * 4 + 2], bl[nfp * 4 + 3], sb + T_WLO * 2 + off);
            }
#pragma unroll
            for (int mf = 0; mf < 4; ++mf) {
                int row = wm * 64 + mf * 16 + a_row;
                uint32_t off = (uint32_t)(row * SSTR + kk + a_kofs) * 2;
                uint32_t ah0, ah1, ah2, ah3, al0, al1, al2, al3;
                ldsm_x4(ah0, ah1, ah2, ah3, sb + T_AHI * 2 + off);
                ldsm_x4(al0, al1, al2, al3, sb + T_ALO * 2 + off);
#pragma unroll
                for (int nf = 0; nf < 4; ++nf) {
                    uint32_t b0h = bh[(nf >> 1) * 4 + (nf & 1) * 2 + 0];
                    uint32_t b1h = bh[(nf >> 1) * 4 + (nf & 1) * 2 + 1];
                    uint32_t b0l = bl[(nf >> 1) * 4 + (nf & 1) * 2 + 0];
                    uint32_t b1l = bl[(nf >> 1) * 4 + (nf & 1) * 2 + 1];
                    mma16816(acc[mf][nf], ah0, ah1, ah2, ah3, b0h, b1h);
                    mma16816(acc[mf][nf], ah0, ah1, ah2, ah3, b0l, b1l);
                    mma16816(acc[mf][nf], al0, al1, al2, al3, b0h, b1h);
                }
            }
        }
        __syncthreads();
        if (ch + 2 < NCH) load_stage(ch & 1, (ch + 2) * 32);
        cp_commit();
    }

    const int mbase = m0 + wm * 64;
    const int nbase = n0 + wn * 32;
    float bs0[4], bs1[4];
#pragma unroll
    for (int nf = 0; nf < 4; ++nf) {
        int c = nbase + nf * 8 + (lane & 3) * 2;
        bs0[nf] = bih[c] + bhh[c];
        bs1[nf] = bih[c + 1] + bhh[c + 1];
    }
#pragma unroll
    for (int mf = 0; mf < 4; ++mf) {
        int row0 = mbase + mf * 16 + (lane >> 2);
#pragma unroll
        for (int nf = 0; nf < 4; ++nf) {
            int col = nbase + nf * 8 + (lane & 3) * 2;
            float2 v0 = make_float2(acc[mf][nf][0] + bs0[nf],
                                    acc[mf][nf][1] + bs1[nf]);
            float2 v1 = make_float2(acc[mf][nf][2] + bs0[nf],
                                    acc[mf][nf][3] + bs1[nf]);
            *reinterpret_cast<float2*>(&C[(size_t)row0 * G4 + col]) = v0;
            *reinterpret_cast<float2*>(&C[(size_t)(row0 + 8) * G4 + col]) = v1;
        }
    }
}

// ---------------- LSTM recurrence: ffma2 + register-resident o-gate ------
// o-gate weights (t-invariant) live in 64 registers/thread for all 256 steps.
// part buffer transposed to [s][r][hc][4] for STS.128/LDS.128.
#define LSTM_SMEM_FLOATS (128*384 + 16*128*4 + 4*128)   // 57856 floats = 231424 B

template<int LAYER>
__global__ __launch_bounds__(256, 1)
void lstm_kernel(const float* __restrict__ xproj,
                 float* __restrict__ out) {
    extern __shared__ float smemf[];
    float* Wsm  = smemf;                      // [128][384] i,f,g gate weights
    float* part = smemf + 128 * 384;          // [16][128][4] transposed partials
    float* hbuf = part + 16 * 128 * 4;        // [4][128]

    const float* Wt = g_Wt[LAYER];            // [128][512]
    const int tid = threadIdx.x;
    const int b0 = blockIdx.x * 4;

    for (int i = tid; i < 128 * 384 / 4; i += 256) {
        int k = i / 96;
        int gc4 = (i % 96) * 4;
        *(float4*)&Wsm[k * 384 + gc4] = *(const float4*)&Wt[k * G4 + gc4];
    }
    for (int i = tid; i < 4 * 128; i += 256) hbuf[i] = 0.0f;
    float creg[2] = {0.0f, 0.0f};

    const int ksl  = tid >> 6;
    const int ggrp = tid & 63;
    const int k0   = ksl * 32;
    const int g2   = ggrp * 2;

    // o-gate weights: 32 u64 pairs, register-resident across all timesteps
    u64t wo[32];
#pragma unroll
    for (int kk = 0; kk < 32; ++kk)
        wo[kk] = *(const u64t*)&Wt[(size_t)(k0 + kk) * G4 + 384 + g2];

    __syncthreads();

    for (int t = 0; t < TSTEPS; ++t) {
        float xv[2][4];
#pragma unroll
        for (int cc = 0; cc < 2; ++cc) {
            int cell = tid + cc * 256;
            int r = cell >> 7, hc = cell & 127;
            const float* xp = xproj + ((size_t)(b0 + r) * TSTEPS + t) * G4 + hc;
            xv[cc][0] = xp[0];   xv[cc][1] = xp[128];
            xv[cc][2] = xp[256]; xv[cc][3] = xp[384];
        }

        u64t acc2[4][4];
#pragma unroll
        for (int r = 0; r < 4; ++r)
#pragma unroll
            for (int jp = 0; jp < 4; ++jp) acc2[r][jp] = 0ull;

        // fully unrolled so wo[kk] stays register-indexed
#pragma unroll
        for (int kk = 0; kk < 32; ++kk) {
            int k = k0 + kk;
            u64t h2[4];
            h2[0] = bcast2(hbuf[k]);
            h2[1] = bcast2(hbuf[128 + k]);
            h2[2] = bcast2(hbuf[256 + k]);
            h2[3] = bcast2(hbuf[384 + k]);
            u64t w0 = *(const u64t*)&Wsm[k * 384 + g2];
            u64t w1 = *(const u64t*)&Wsm[k * 384 + 128 + g2];
            u64t w2 = *(const u64t*)&Wsm[k * 384 + 256 + g2];
            u64t w3 = wo[kk];
#pragma unroll
            for (int r = 0; r < 4; ++r) {
                ffma2(acc2[r][0], h2[r], w0);
                ffma2(acc2[r][1], h2[r], w1);
                ffma2(acc2[r][2], h2[r], w2);
                ffma2(acc2[r][3], h2[r], w3);
            }
        }
        // transposed partial store: part[(ksl*4+r)*128 + hc][0..3] via STS.128
#pragma unroll
        for (int r = 0; r < 4; ++r) {
            float4 lo4 = make_float4(lo_f(acc2[r][0]), lo_f(acc2[r][1]),
                                     lo_f(acc2[r][2]), lo_f(acc2[r][3]));
            float4 hi4 = make_float4(hi_f(acc2[r][0]), hi_f(acc2[r][1]),
                                     hi_f(acc2[r][2]), hi_f(acc2[r][3]));
            float* pb = &part[(size_t)((ksl * 4 + r) * 128 + g2) * 4];
            *reinterpret_cast<float4*>(pb) = lo4;
            *reinterpret_cast<float4*>(pb + 4) = hi4;
        }
        __syncthreads();

#pragma unroll
        for (int cc = 0; cc < 2; ++cc) {
            int cell = tid + cc * 256;
            int r = cell >> 7, hc = cell & 127;
            float4 p0 = *reinterpret_cast<const float4*>(
                &part[(size_t)((0 * 4 + r) * 128 + hc) * 4]);
            float4 p1 = *reinterpret_cast<const float4*>(
                &part[(size_t)((1 * 4 + r) * 128 + hc) * 4]);
            float4 p2 = *reinterpret_cast<const float4*>(
                &part[(size_t)((2 * 4 + r) * 128 + hc) * 4]);
            float4 p3 = *reinterpret_cast<const float4*>(
                &part[(size_t)((3 * 4 + r) * 128 + hc) * 4]);
            float gi = xv[cc][0] + p0.x + p1.x + p2.x + p3.x;
            float gf = xv[cc][1] + p0.y + p1.y + p2.y + p3.y;
            float gg = xv[cc][2] + p0.z + p1.z + p2.z + p3.z;
            float go = xv[cc][3] + p0.w + p1.w + p2.w + p3.w;
            float iv = sigmoidf_(gi);
            float fv = sigmoidf_(gf);
            float gv = tanhf_(gg);
            float ov = sigmoidf_(go);
            float c = fv * creg[cc] + iv * gv;
            creg[cc] = c;
            float h = ov * tanhf_(c);
            hbuf[r * 128 + hc] = h;
            if (LAYER == 0) {
                size_t o = ((size_t)(b0 + r) * TSTEPS + t) * HID + hc;
                __nv_bfloat16 hb = __float2bfloat16(h);
                g_h_hi[o] = hb;
                g_h_lo[o] = __float2bfloat16(h - __bfloat162float(hb));
            }
        }
        __syncthreads();
    }

#pragma unroll
    for (int cc = 0; cc < 2; ++cc) {
        int cell = tid + cc * 256;
        int r = cell >> 7, hc = cell & 127;
        int bi = b0 + r;
        out[OUT_HN_OFF + LAYER * BATCH * HID + bi * HID + hc] = hbuf[r * 128 + hc];
        out[OUT_CN_OFF + LAYER * BATCH * HID + bi * HID + hc] = creg[cc];
    }
}

// ---------------- head: relu(h@fc1^T+b1)@fc2^T+b2 -> softmax ----------------
__global__ __launch_bounds__(256)
void head_kernel(const float* __restrict__ fc1w, const float* __restrict__ fc1b,
                 const float* __restrict__ fc2w, const float* __restrict__ fc2b,
                 float* __restrict__ out) {
    __shared__ float sw1[FC1DIM * HID];
    __shared__ float sw2[NACT * FC1DIM];
    __shared__ float sb1[FC1DIM];
    __shared__ float sb2[NACT];

    for (int i = threadIdx.x; i < FC1DIM * HID; i += 256) sw1[i] = fc1w[i];
    for (int i = threadIdx.x; i < NACT * FC1DIM; i += 256) sw2[i] = fc2w[i];
    if (threadIdx.x < FC1DIM) sb1[threadIdx.x] = fc1b[threadIdx.x];
    if (threadIdx.x < NACT) sb2[threadIdx.x] = fc2b[threadIdx.x];
    __syncthreads();

    int row = blockIdx.x * 256 + threadIdx.x;
    const float* h = out + OUT_HN_OFF + BATCH * HID + row * HID;

    float hid[FC1DIM];
#pragma unroll
    for (int j = 0; j < FC1DIM; ++j) hid[j] = sb1[j];
    for (int k = 0; k < HID; ++k) {
        float hv = h[k];
#pragma unroll
        for (int j = 0; j < FC1DIM; ++j)
            hid[j] += hv * sw1[j * HID + k];
    }
#pragma unroll
    for (int j = 0; j < FC1DIM; ++j) hid[j] = fmaxf(hid[j], 0.0f);

    float logit[NACT];
    float mx = -1e30f;
#pragma unroll
    for (int a = 0; a < NACT; ++a) {
        float l = sb2[a];
#pragma unroll
        for (int j = 0; j < FC1DIM; ++j)
            l += hid[j] * sw2[a * FC1DIM + j];
        logit[a] = l;
        mx = fmaxf(mx, l);
    }
    float sum = 0.0f;
#pragma unroll
    for (int a = 0; a < NACT; ++a) {
        logit[a] = __expf(logit[a] - mx);
        sum += logit[a];
    }
    float inv = 1.0f / sum;
#pragma unroll
    for (int a = 0; a < NACT; ++a)
        out[row * NACT + a] = logit[a] * inv;
}

// ---------------- launch ----------------
extern "C" void kernel_launch(void* const* d_in, const int* in_sizes, int n_in,
                              void* d_out, int out_size) {
    (void)in_sizes; (void)n_in; (void)out_size;
    const float* x     = (const float*)d_in[0];
    const float* Wih0  = (const float*)d_in[1];
    const float* Whh0  = (const float*)d_in[2];
    const float* bih0  = (const float*)d_in[3];
    const float* bhh0  = (const float*)d_in[4];
    const float* Wih1  = (const float*)d_in[5];
    const float* Whh1  = (const float*)d_in[6];
    const float* bih1  = (const float*)d_in[7];
    const float* bhh1  = (const float*)d_in[8];
    const float* fc1w  = (const float*)d_in[9];
    const float* fc1b  = (const float*)d_in[10];
    const float* fc2w  = (const float*)d_in[11];
    const float* fc2b  = (const float*)d_in[12];
    float* out = (float*)d_out;

    float* xproj = nullptr;
    __nv_bfloat16 *xhi, *xlo, *hhi, *hlo, *w0hi, *w0lo, *w1hi, *w1lo;
    cudaGetSymbolAddress((void**)&xproj, g_xproj);
    cudaGetSymbolAddress((void**)&xhi, g_x_hi);
    cudaGetSymbolAddress((void**)&xlo, g_x_lo);
    cudaGetSymbolAddress((void**)&hhi, g_h_hi);
    cudaGetSymbolAddress((void**)&hlo, g_h_lo);
    cudaGetSymbolAddress((void**)&w0hi, g_Wih0_hi);
    cudaGetSymbolAddress((void**)&w0lo, g_Wih0_lo);
    cudaGetSymbolAddress((void**)&w1hi, g_Wih1_hi);
    cudaGetSymbolAddress((void**)&w1lo, g_Wih1_lo);

    cudaFuncSetAttribute(lstm_kernel<0>,
                         cudaFuncAttributeMaxDynamicSharedMemorySize,
                         LSTM_SMEM_FLOATS * 4);
    cudaFuncSetAttribute(lstm_kernel<1>,
                         cudaFuncAttributeMaxDynamicSharedMemorySize,
                         LSTM_SMEM_FLOATS * 4);
    cudaFuncSetAttribute(gemm_mma_kernel<INPUT>,
                         cudaFuncAttributeMaxDynamicSharedMemorySize, GEMM_SMEM);
    cudaFuncSetAttribute(gemm_mma_kernel<HID>,
                         cudaFuncAttributeMaxDynamicSharedMemorySize, GEMM_SMEM);

    // 1) weight prep + x split
    prep_weights_kernel<<<1024, 256>>>(Whh0, Whh1, Wih0, Wih1);
    split_x_kernel<<<MROWS * INPUT / 4 / 256, 256>>>(x);

    // 2) x_proj0 = x @ Wih0^T + bias (tensor cores, double-buffered)
    gemm_mma_kernel<INPUT><<<dim3(4, MROWS / 128), 256, GEMM_SMEM>>>(
        xhi, xlo, w0hi, w0lo, bih0, bhh0, xproj);

    // 3) layer-0 recurrence (writes h seq as bf16 hi/lo)
    lstm_kernel<0><<<BATCH / 4, 256, LSTM_SMEM_FLOATS * 4>>>(xproj, out);

    // 4) x_proj1 = h0_seq @ Wih1^T + bias
    gemm_mma_kernel<HID><<<dim3(4, MROWS / 128), 256, GEMM_SMEM>>>(
        hhi, hlo, w1hi, w1lo, bih1, bhh1, xproj);

    // 5) layer-1 recurrence
    lstm_kernel<1><<<BATCH / 4, 256, LSTM_SMEM_FLOATS * 4>>>(xproj, out);

    // 6) head
    head_kernel<<<2, 256>>>(fc1w, fc1b, fc2w, fc2b, out);
}